// round 13
// baseline (speedup 1.0000x reference)
#include <cuda_runtime.h>
#include <cuda_fp16.h>
#include <math.h>

#define B_  8
#define L_  1024
#define D_  512
#define H_  8
#define DH_ 64
#define M_  (B_*L_)     // 8192
#define BH_ (B_*H_)     // 64

// Scratch (device globals: allocation-free kernel_launch per harness rules)
__device__ __align__(16) __half g_Qh[BH_*L_*DH_];  // fp16, 0.125*log2e-scaled
__device__ __align__(16) __half g_Kh[BH_*L_*DH_];
__device__ __align__(16) __half g_Vh[BH_*L_*DH_];
__device__ __align__(16) __half g_Ctxh[M_*D_];     // fp16, (b,l,D)
__device__ __align__(16) __half g_xh[M_*D_];       // fp16 inputs
__device__ __align__(16) __half g_Wqh[D_*D_];
__device__ __align__(16) __half g_Wkh[D_*D_];
__device__ __align__(16) __half g_Wvh[D_*D_];
__device__ __align__(16) __half g_Woh[D_*D_];
__device__ __align__(16) __half g_Weh[L_*DH_];
__device__ __align__(16) __half g_R[(size_t)BH_*L_*L_ + 128]; // bias (log2 domain), padded

// ---------------------------------------------------------------------------
// helpers
// ---------------------------------------------------------------------------
__device__ __forceinline__ void mma16h(float* c,
    unsigned a0, unsigned a1, unsigned a2, unsigned a3,
    unsigned b0, unsigned b1)
{
    asm volatile(
        "mma.sync.aligned.m16n8k16.row.col.f32.f16.f16.f32 "
        "{%0,%1,%2,%3},{%4,%5,%6,%7},{%8,%9},{%0,%1,%2,%3};"
        : "+f"(c[0]), "+f"(c[1]), "+f"(c[2]), "+f"(c[3])
        : "r"(a0), "r"(a1), "r"(a2), "r"(a3), "r"(b0), "r"(b1));
}
__device__ __forceinline__ void ldsm4(unsigned& r0, unsigned& r1,
                                      unsigned& r2, unsigned& r3, unsigned addr)
{
    asm volatile("ldmatrix.sync.aligned.m8n8.x4.shared.b16 {%0,%1,%2,%3}, [%4];"
        : "=r"(r0), "=r"(r1), "=r"(r2), "=r"(r3) : "r"(addr));
}
__device__ __forceinline__ void ldsm4t(unsigned& r0, unsigned& r1,
                                       unsigned& r2, unsigned& r3, unsigned addr)
{
    asm volatile("ldmatrix.sync.aligned.m8n8.x4.trans.shared.b16 {%0,%1,%2,%3}, [%4];"
        : "=r"(r0), "=r"(r1), "=r"(r2), "=r"(r3) : "r"(addr));
}
// 2^x for two values via MUFU (XU pipe)
__device__ __forceinline__ unsigned ex2h2(float lo, float hi) {
    unsigned p;
    asm("cvt.rn.f16x2.f32 %0, %1, %2;" : "=r"(p) : "f"(hi), "f"(lo));
    asm("ex2.approx.f16x2 %0, %0;" : "+r"(p));
    return p;
}
// 2^x in fp32 on FMA/ALU pipes: magic-add round, quartic 2^f, exponent inject.
// Valid for x in (-120, 120); rel err <= ~4e-5.
__device__ __forceinline__ float ex2f(float z) {
    float m  = z + 12582912.0f;          // rni(z) in low mantissa (1.5*2^23)
    float zi = m - 12582912.0f;
    float f  = z - zi;                   // [-0.5, 0.5]
    float p  = fmaf(f, 0.00961804f, 0.05550411f);
    p = fmaf(f, p, 0.24022651f);
    p = fmaf(f, p, 0.69314718f);
    p = fmaf(f, p, 1.0f);                // 2^f
    // bits(m)<<23 == zi<<23 (low 9 bits of 0x4B400000 are 0)
    return __int_as_float(__float_as_int(p) + (__float_as_int(m) << 23));
}
__device__ __forceinline__ unsigned ex2p2(float lo, float hi) {
    float a = ex2f(lo), b = ex2f(hi);
    unsigned p;
    asm("cvt.rn.f16x2.f32 %0, %1, %2;" : "=r"(p) : "f"(b), "f"(a));
    return p;
}
__device__ __forceinline__ unsigned scvta(const void* p) {
    return (unsigned)__cvta_generic_to_shared(p);
}
__device__ __forceinline__ void cpa16(unsigned dst, const void* src) {
    asm volatile("cp.async.cg.shared.global [%0], [%1], 16;" :: "r"(dst), "l"(src));
}
__device__ __forceinline__ void cpa_commit() {
    asm volatile("cp.async.commit_group;");
}
template<int N> __device__ __forceinline__ void cpa_wait() {
    asm volatile("cp.async.wait_group %0;" :: "n"(N));
}

// ---------------------------------------------------------------------------
// Prep: ONE launch converting all inputs to fp16
// ---------------------------------------------------------------------------
#define XN_ (M_*D_)
#define WN_ (D_*D_)
__global__ void __launch_bounds__(256) prep_kernel(
    const float* __restrict__ x,  const float* __restrict__ Wq,
    const float* __restrict__ Wk, const float* __restrict__ Wv,
    const float* __restrict__ Wo, const float* __restrict__ We)
{
    int i = (blockIdx.x * 256 + threadIdx.x) * 4;
    if (i >= XN_ + 4*WN_ + L_*DH_) return;
    const float* s; __half* d;
    if      (i < XN_)          { s = x  + i;               d = g_xh  + i; }
    else if (i < XN_ + WN_)    { s = Wq + i - XN_;         d = g_Wqh + i - XN_; }
    else if (i < XN_ + 2*WN_)  { s = Wk + i - XN_ - WN_;   d = g_Wkh + i - XN_ - WN_; }
    else if (i < XN_ + 3*WN_)  { s = Wv + i - XN_ - 2*WN_; d = g_Wvh + i - XN_ - 2*WN_; }
    else if (i < XN_ + 4*WN_)  { s = Wo + i - XN_ - 3*WN_; d = g_Woh + i - XN_ - 3*WN_; }
    else                       { s = We + i - XN_ - 4*WN_; d = g_Weh + i - XN_ - 4*WN_; }
    float4 v = *(const float4*)s;
    *(__half2*)(d)     = __floats2half2_rn(v.x, v.y);
    *(__half2*)(d + 2) = __floats2half2_rn(v.z, v.w);
}

// ---------------------------------------------------------------------------
// Dense fp16 GEMM body (K=512): C(128x128) = A * W^T, fp32 accum.
// 3-stage cp.async, ldmatrix frags, pitch 40 halves (conflict-free).
// ---------------------------------------------------------------------------
__device__ __forceinline__ void gemm_body_h(
    const __half* __restrict__ A, const __half* __restrict__ W,
    int mBase, int nBase, __half* As, __half* Bs, float C[2][8][4])
{
    const int t = threadIdx.x, lane = t & 31, warp = t >> 5;
    const int wm = warp >> 1, wn = warp & 1;
    const int srow = t >> 1, sc = (t & 1) * 2;
    const int BUF = 128 * 40;

    unsigned a_a = scvta(As) + (unsigned)(srow * 80);
    unsigned b_a = scvta(Bs) + (unsigned)(srow * 80);

    auto stage = [&](int buf, int k0) {
        unsigned off = (unsigned)(buf * BUF * 2);
        #pragma unroll
        for (int i = 0; i < 2; i++) {
            int ci = sc + i;
            cpa16(a_a + off + ci*16, A + (size_t)(mBase + srow) * D_ + k0 + ci*8);
            cpa16(b_a + off + ci*16, W + (size_t)(nBase + srow) * D_ + k0 + ci*8);
        }
        cpa_commit();
    };

    const int lr8 = lane & 7;
    unsigned aAddr = scvta(As) +
        (unsigned)(((wm*32 + (lane & 15))*40 + (lane >> 4)*8) * 2);
    unsigned bAddr = scvta(Bs) +
        (unsigned)(((wn*64 + lr8 + ((lane & 16) ? 8 : 0))*40 + ((lane & 8) ? 8 : 0)) * 2);

    stage(0, 0);
    stage(1, 32);
    int cb = 0, nb = 2, nk = 64;
    for (int it = 0; it < 16; it++) {
        if (it == 15) cpa_wait<0>(); else cpa_wait<1>();
        __syncthreads();
        if (it + 2 < 16) {
            stage(nb, nk);
            nk += 32;
            nb = (nb == 2) ? 0 : nb + 1;
        }
        const unsigned bo = (unsigned)(cb * BUF * 2);
        #pragma unroll
        for (int kk = 0; kk < 32; kk += 16) {
            unsigned a[2][4];
            #pragma unroll
            for (int mi = 0; mi < 2; mi++)
                ldsm4(a[mi][0], a[mi][1], a[mi][2], a[mi][3],
                      aAddr + bo + (unsigned)((mi*16*40 + kk) * 2));
            #pragma unroll
            for (int jp = 0; jp < 4; jp++) {
                unsigned b0, b1, b2, b3;
                ldsm4(b0, b1, b2, b3, bAddr + bo + (unsigned)((jp*16*40 + kk) * 2));
                mma16h(C[0][jp*2],   a[0][0], a[0][1], a[0][2], a[0][3], b0, b1);
                mma16h(C[0][jp*2+1], a[0][0], a[0][1], a[0][2], a[0][3], b2, b3);
                mma16h(C[1][jp*2],   a[1][0], a[1][1], a[1][2], a[1][3], b0, b1);
                mma16h(C[1][jp*2+1], a[1][0], a[1][1], a[1][2], a[1][3], b2, b3);
            }
        }
        cb = (cb == 2) ? 0 : cb + 1;
    }
}

// ---------------------------------------------------------------------------
// Kernel: QKV projections -> fp16 (b,h,l,dh). Q scaled by 0.125*log2(e).
// ---------------------------------------------------------------------------
__global__ void __launch_bounds__(256, 2) qkv_kernel()
{
    extern __shared__ __half smqh[];
    __half* As = smqh;
    __half* Bs = smqh + 3*128*40;
    const __half* W = (blockIdx.z == 0) ? g_Wqh : (blockIdx.z == 1) ? g_Wkh : g_Wvh;
    __half* dst     = (blockIdx.z == 0) ? g_Qh  : (blockIdx.z == 1) ? g_Kh  : g_Vh;
    const float scale = (blockIdx.z == 0) ? 0.125f * 1.4426950408889634f : 1.0f;
    const int mBase = blockIdx.x * 128, nBase = blockIdx.y * 128;
    float C[2][8][4] = {};
    gemm_body_h(g_xh, W, mBase, nBase, As, Bs, C);

    const int t = threadIdx.x, lane = t & 31, warp = t >> 5;
    const int g = lane >> 2, tg = lane & 3;
    const int wm = warp >> 1, wn = warp & 1;
    #pragma unroll
    for (int mi = 0; mi < 2; mi++) {
        #pragma unroll
        for (int j = 0; j < 8; j++) {
            int n = nBase + wn*64 + j*8 + 2*tg;
            int h = n >> 6, dh = n & 63;
            #pragma unroll
            for (int hh = 0; hh < 2; hh++) {
                int m = mBase + wm*32 + mi*16 + g + 8*hh;
                int b = m >> 10, l = m & (L_-1);
                __half2 v = __floats2half2_rn(C[mi][j][hh*2]*scale, C[mi][j][hh*2+1]*scale);
                *(__half2*)(dst + ((size_t)((b*H_+h)*L_ + l))*DH_ + dh) = v;
            }
        }
    }
}

// ---------------------------------------------------------------------------
// Kernel: R[bh][l][e] = Qh[bh,l,:].Weh[e,:] (fp16 mma, K=64), fp16 output
// ---------------------------------------------------------------------------
__global__ void __launch_bounds__(256, 2) rel_kernel()
{
    extern __shared__ __half smr[];
    __half* Ah = smr;               // 128 x 72 halves
    __half* Bh = smr + 128*72;
    const int bh = blockIdx.z;
    const int mBase = blockIdx.x * 128, nBase = blockIdx.y * 128;
    const __half* A  = g_Qh + (size_t)bh * L_ * DH_;
    const __half* Wb = g_Weh;

    const int t = threadIdx.x, lane = t & 31, warp = t >> 5;
    const int wm = warp >> 1, wn = warp & 1;

    const int lr2 = t >> 1, lc2 = (t & 1) * 4;
    unsigned a_a = scvta(Ah) + (unsigned)(lr2*144);
    unsigned b_a = scvta(Bh) + (unsigned)(lr2*144);
    #pragma unroll
    for (int i = 0; i < 4; i++) {
        int ci = lc2 + i;
        cpa16(a_a + ci*16, A  + (size_t)(mBase + lr2) * DH_ + ci*8);
        cpa16(b_a + ci*16, Wb + (size_t)(nBase + lr2) * DH_ + ci*8);
    }
    cpa_commit(); cpa_wait<0>();
    __syncthreads();

    const int lr8 = lane & 7;
    unsigned aAddr = scvta(Ah) +
        (unsigned)(((wm*32 + (lane & 15))*72 + ((lane >> 4)*8)) * 2);
    unsigned bAddr = scvta(Bh) +
        (unsigned)(((wn*64 + lr8 + ((lane & 16) ? 8 : 0))*72 + ((lane & 8) ? 8 : 0)) * 2);

    float C[2][8][4] = {};
    #pragma unroll
    for (int k0 = 0; k0 < 64; k0 += 16) {
        unsigned a[2][4];
        #pragma unroll
        for (int mi = 0; mi < 2; mi++)
            ldsm4(a[mi][0], a[mi][1], a[mi][2], a[mi][3],
                  aAddr + (unsigned)((mi*16*72 + k0) * 2));
        #pragma unroll
        for (int jp = 0; jp < 4; jp++) {
            unsigned b0, b1, b2, b3;
            ldsm4(b0, b1, b2, b3, bAddr + (unsigned)((jp*16*72 + k0) * 2));
            mma16h(C[0][jp*2],   a[0][0], a[0][1], a[0][2], a[0][3], b0, b1);
            mma16h(C[0][jp*2+1], a[0][0], a[0][1], a[0][2], a[0][3], b2, b3);
            mma16h(C[1][jp*2],   a[1][0], a[1][1], a[1][2], a[1][3], b0, b1);
            mma16h(C[1][jp*2+1], a[1][0], a[1][1], a[1][2], a[1][3], b2, b3);
        }
    }

    const int g = lane >> 2, tg = lane & 3;
    __half* Rb = g_R + (size_t)bh * L_ * L_;
    #pragma unroll
    for (int mi = 0; mi < 2; mi++) {
        #pragma unroll
        for (int j = 0; j < 8; j++) {
            int n = nBase + wn*64 + j*8 + 2*tg;
            #pragma unroll
            for (int hh = 0; hh < 2; hh++) {
                int m = mBase + wm*32 + mi*16 + g + 8*hh;
                __half2 v = __floats2half2_rn(C[mi][j][hh*2], C[mi][j][hh*2+1]);
                *(__half2*)(Rb + (size_t)m*L_ + n) = v;
            }
        }
    }
}

// ---------------------------------------------------------------------------
// Kernel: flash attention. 256 threads, 128-row q-tiles, double-buffered
// K/V/bias staging, all-fp16 mma. Exponentials split across pipes:
// even j2-blocks via MUFU (ex2.f16x2), odd via FMA/ALU polynomial.
// ---------------------------------------------------------------------------
__global__ void __launch_bounds__(256, 2) attn_kernel()
{
    extern __shared__ __half sma[];
    __half* Qh = sma;                    // 128 x 72
    __half* Kh = Qh + 128*72;            // 2 buf x 64 x 72
    __half* Vh = Kh + 2*64*72;           // 2 buf x 64 x 72
    __half* Rw = Vh + 2*64*72;           // 2 buf x 128 x 80

    const int KVB = 64*72;
    const int RWB = 128*80;

    const int bh = blockIdx.y, lBase = blockIdx.x * 128;
    const __half* __restrict__ Qg = g_Qh + (size_t)bh * L_ * DH_;
    const __half* __restrict__ Kg = g_Kh + (size_t)bh * L_ * DH_;
    const __half* __restrict__ Vg = g_Vh + (size_t)bh * L_ * DH_;
    const __half* __restrict__ Rg = g_R + ((size_t)bh << 20);

    const int t = threadIdx.x, lane = t & 31, warp = t >> 5;
    const int g = lane >> 2, tg = lane & 3;
    const int rA = warp*16 + g;          // 0..127

    const int qrow = t >> 1, qcb = (t & 1) * 4;
    const int krow = t & 63, kcb = (t >> 6) * 2;
    const int rrow = t >> 1, rcb = (t & 1) * 5;
    unsigned q_a = scvta(Qh) + (unsigned)(qrow*144);
    unsigned k_a = scvta(Kh) + (unsigned)(krow*144);
    unsigned v_a = scvta(Vh) + (unsigned)(krow*144);
    unsigned r_a = scvta(Rw) + (unsigned)(rrow*160);
    const int rl = lBase + rrow;
    const __half* Rrow = Rg + ((size_t)rl << 10);

    auto admax = [](int l, int sB) {
        int a0 = l - sB;      if (a0 < 0) a0 = -a0;
        int a1 = l - sB - 63; if (a1 < 0) a1 = -a1;
        return a0 > a1 ? a0 : a1;
    };

    auto stage_kvr = [&](int buf, int sB) {
        unsigned kvoff = (unsigned)(buf * KVB * 2);
        unsigned rwoff = (unsigned)(buf * RWB * 2);
        #pragma unroll
        for (int i = 0; i < 2; i++) {
            int ci = kcb + i;
            cpa16(k_a + kvoff + ci*16, Kg + (size_t)(sB + krow)*DH_ + ci*8);
            cpa16(v_a + kvoff + ci*16, Vg + (size_t)(sB + krow)*DH_ + ci*8);
        }
        int e_lo8 = (1023 - admax(rl, sB)) & ~7;
        #pragma unroll
        for (int i = 0; i < 5; i++) {
            int ci = rcb + i;
            cpa16(r_a + rwoff + ci*16, Rrow + e_lo8 + ci*8);
        }
        cpa_commit();
    };

    {   // stage Q (once) + tile 0 into buffer 0
        #pragma unroll
        for (int i = 0; i < 4; i++) {
            int ci = qcb + i;
            cpa16(q_a + ci*16, Qg + (size_t)(lBase + qrow)*DH_ + ci*8);
        }
        stage_kvr(0, 0);
    }

    const int lr8 = lane & 7;
    unsigned aQ = scvta(Qh) +
        (unsigned)(((warp*16 + (lane & 15))*72 + ((lane >> 4)*8)) * 2);
    unsigned bK0 = scvta(Kh) +
        (unsigned)(((lr8 + ((lane & 16) ? 8 : 0))*72 + ((lane & 8) ? 8 : 0)) * 2);
    unsigned bV0 = scvta(Vh) +
        (unsigned)(((lane & 15)*72 + (lane >> 4)*8) * 2);

    const unsigned ONES = 0x3C003C00u;
    float lsum[4] = {0.f, 0.f, 0.f, 0.f};
    float O[8][4] = {};

    const int lg0 = lBase + rA, lg1 = lg0 + 8;

    for (int it = 0; it < 16; it++) {
        const int sBase = it * 64;
        const int buf = it & 1;

        cpa_wait<0>();
        __syncthreads();                                    // tile `it` staged

        if (it + 1 < 16)                                    // overlap: stage i+1
            stage_kvr(buf ^ 1, sBase + 64);

        const unsigned kvoff = (unsigned)(buf * KVB * 2);
        const __half* Rb = Rw + buf * RWB;

        // ---- sf init: bias gather from staged windows ----
        float sf[8][4];
        if (lBase >= sBase + 64) {
            const __half* p0 = Rb + rA*80     + ((1023 - lg0 + sBase) & 7) + 2*tg;
            const __half* p1 = Rb + (rA+8)*80 + ((1023 - lg1 + sBase) & 7) + 2*tg;
            #pragma unroll
            for (int j = 0; j < 8; j++) {
                sf[j][0] = __half2float(p0[j*8]);
                sf[j][1] = __half2float(p0[j*8 + 1]);
                sf[j][2] = __half2float(p1[j*8]);
                sf[j][3] = __half2float(p1[j*8 + 1]);
            }
        } else if (sBase >= lBase + 128) {
            const __half* p0 = Rb + rA*80     + ((960 - sBase + lg0) & 7) + 63 - 2*tg;
            const __half* p1 = Rb + (rA+8)*80 + ((960 - sBase + lg1) & 7) + 63 - 2*tg;
            #pragma unroll
            for (int j = 0; j < 8; j++) {
                sf[j][0] = __half2float(p0[-(j*8)]);
                sf[j][1] = __half2float(p0[-(j*8) - 1]);
                sf[j][2] = __half2float(p1[-(j*8)]);
                sf[j][3] = __half2float(p1[-(j*8) - 1]);
            }
        } else {
            const int base0 = 1023 - ((1023 - admax(lg0, sBase)) & ~7);
            const int base1 = 1023 - ((1023 - admax(lg1, sBase)) & ~7);
            #pragma unroll
            for (int j = 0; j < 8; j++) {
                int c0 = sBase + j*8 + 2*tg;
                #pragma unroll
                for (int q = 0; q < 4; q++) {
                    int col  = c0 + (q & 1);
                    int lg   = (q < 2) ? lg0 : lg1;
                    int rloc = (q < 2) ? rA  : rA + 8;
                    int base = (q < 2) ? base0 : base1;
                    int d = lg - col; int ad = d < 0 ? -d : d;
                    sf[j][q] = __half2float(Rb[rloc*80 + base - ad]);
                }
            }
        }

        // ---- S GEMM (fp16, accumulates onto bias) ----
        #pragma unroll
        for (int k0 = 0; k0 < 64; k0 += 16) {
            unsigned a0, a1, a2, a3;
            ldsm4(a0, a1, a2, a3, aQ + (unsigned)(k0*2));
            #pragma unroll
            for (int jp = 0; jp < 4; jp++) {
                unsigned b0, b1, b2, b3;
                ldsm4(b0, b1, b2, b3, bK0 + kvoff + (unsigned)((jp*16*72 + k0) * 2));
                mma16h(sf[jp*2],   a0, a1, a2, a3, b0, b1);
                mma16h(sf[jp*2+1], a0, a1, a2, a3, b2, b3);
            }
        }

        // ---- softmax tail (XU/FMA split) + PV ----
        #pragma unroll
        for (int j2 = 0; j2 < 4; j2++) {
            const int jb0 = 2*j2, jb1 = 2*j2 + 1;
            unsigned a0, a1, a2, a3;
            if (j2 & 1) {   // FMA/ALU polynomial path
                a0 = ex2p2(sf[jb0][0], sf[jb0][1]);
                a1 = ex2p2(sf[jb0][2], sf[jb0][3]);
                a2 = ex2p2(sf[jb1][0], sf[jb1][1]);
                a3 = ex2p2(sf[jb1][2], sf[jb1][3]);
            } else {        // MUFU path
                a0 = ex2h2(sf[jb0][0], sf[jb0][1]);
                a1 = ex2h2(sf[jb0][2], sf[jb0][3]);
                a2 = ex2h2(sf[jb1][0], sf[jb1][1]);
                a3 = ex2h2(sf[jb1][2], sf[jb1][3]);
            }
            mma16h(lsum, a0, a1, a2, a3, ONES, ONES);
            #pragma unroll
            for (int jp = 0; jp < 4; jp++) {
                unsigned b0, b1, b2, b3;
                ldsm4t(b0, b1, b2, b3, bV0 + kvoff + (unsigned)((j2*16*72 + jp*16) * 2));
                mma16h(O[jp*2],   a0, a1, a2, a3, b0, b1);
                mma16h(O[jp*2+1], a0, a1, a2, a3, b2, b3);
            }
        }
        // buffer reuse protected by next iteration's top sync
    }

    // normalize + write ctx (fp16)
    const float i0 = 1.0f / lsum[0], i1 = 1.0f / lsum[2];
    const int b = bh >> 3, hh = bh & 7;
    #pragma unroll
    for (int j = 0; j < 8; j++) {
        int dh = j*8 + 2*tg;
        size_t base0 = ((size_t)(b*L_ + lBase + rA))*D_ + hh*DH_ + dh;
        size_t base1 = ((size_t)(b*L_ + lBase + rA + 8))*D_ + hh*DH_ + dh;
        *(__half2*)(g_Ctxh + base0) = __floats2half2_rn(O[j][0]*i0, O[j][1]*i0);
        *(__half2*)(g_Ctxh + base1) = __floats2half2_rn(O[j][2]*i1, O[j][3]*i1);
    }
}

// ---------------------------------------------------------------------------
// Kernel: out = Ctx @ Wo^T + bo   (fp16 GEMM, fp32 out)
// ---------------------------------------------------------------------------
__global__ void __launch_bounds__(256, 2) out_kernel(
    const float* __restrict__ bo, float* __restrict__ out)
{
    extern __shared__ __half smqh[];
    __half* As = smqh;
    __half* Bs = smqh + 3*128*40;
    const int mBase = blockIdx.x * 128, nBase = blockIdx.y * 128;
    float C[2][8][4] = {};
    gemm_body_h(g_Ctxh, g_Woh, mBase, nBase, As, Bs, C);

    const int t = threadIdx.x, lane = t & 31, warp = t >> 5;
    const int g = lane >> 2, tg = lane & 3;
    const int wm = warp >> 1, wn = warp & 1;
    #pragma unroll
    for (int mi = 0; mi < 2; mi++) {
        #pragma unroll
        for (int j = 0; j < 8; j++) {
            int n = nBase + wn*64 + j*8 + 2*tg;
            float2 bias = *(const float2*)(bo + n);
            #pragma unroll
            for (int hh = 0; hh < 2; hh++) {
                int m = mBase + wm*32 + mi*16 + g + 8*hh;
                float2 v = make_float2(C[mi][j][hh*2] + bias.x, C[mi][j][hh*2+1] + bias.y);
                *(float2*)(out + (size_t)m*D_ + n) = v;
            }
        }
    }
}

// ---------------------------------------------------------------------------
extern "C" void kernel_launch(void* const* d_in, const int* in_sizes, int n_in,
                              void* d_out, int out_size)
{
    const float* x  = (const float*)d_in[0];
    const float* Wq = (const float*)d_in[1];
    const float* Wk = (const float*)d_in[2];
    const float* Wv = (const float*)d_in[3];
    const float* We = (const float*)d_in[4];
    const float* Wo = (const float*)d_in[5];
    const float* bo = (const float*)d_in[6];
    float* out = (float*)d_out;

    const int gemm_smem = 2 * 3 * 128 * 40 * (int)sizeof(__half);        // 61440
    const int rel_smem  = 2 * 128 * 72 * (int)sizeof(__half);            // 36864
    const int attn_smem = (128*72 + 2*64*72 + 2*64*72 + 2*128*80)
                          * (int)sizeof(__half);                         // 96256
    cudaFuncSetAttribute(qkv_kernel,  cudaFuncAttributeMaxDynamicSharedMemorySize, gemm_smem);
    cudaFuncSetAttribute(rel_kernel,  cudaFuncAttributeMaxDynamicSharedMemorySize, rel_smem);
    cudaFuncSetAttribute(attn_kernel, cudaFuncAttributeMaxDynamicSharedMemorySize, attn_smem);
    cudaFuncSetAttribute(out_kernel,  cudaFuncAttributeMaxDynamicSharedMemorySize, gemm_smem);

    const int prep_total = XN_ + 4*WN_ + L_*DH_;
    prep_kernel<<<(prep_total/4 + 255)/256, 256>>>(x, Wq, Wk, Wv, Wo, We);

    qkv_kernel<<<dim3(M_/128, D_/128, 3), 256, gemm_smem>>>();
    rel_kernel<<<dim3(L_/128, L_/128, BH_), 256, rel_smem>>>();
    attn_kernel<<<dim3(L_/128, BH_), 256, attn_smem>>>();
    out_kernel<<<dim3(M_/128, D_/128), 256, gemm_smem>>>(bo, out);
}

// round 15
// speedup vs baseline: 1.0639x; 1.0639x over previous
#include <cuda_runtime.h>
#include <cuda_fp16.h>
#include <math.h>

#define B_  8
#define L_  1024
#define D_  512
#define H_  8
#define DH_ 64
#define M_  (B_*L_)     // 8192
#define BH_ (B_*H_)     // 64

// Scratch (device globals: allocation-free kernel_launch per harness rules)
__device__ __align__(16) __half g_Qh[BH_*L_*DH_];  // fp16, 0.125*log2e-scaled
__device__ __align__(16) __half g_Kh[BH_*L_*DH_];
__device__ __align__(16) __half g_Vh[BH_*L_*DH_];
__device__ __align__(16) __half g_Ctxh[M_*D_];     // fp16, (b,l,D)
__device__ __align__(16) __half g_xh[M_*D_];       // fp16 inputs
__device__ __align__(16) __half g_Wqh[D_*D_];
__device__ __align__(16) __half g_Wkh[D_*D_];
__device__ __align__(16) __half g_Wvh[D_*D_];
__device__ __align__(16) __half g_Woh[D_*D_];
__device__ __align__(16) __half g_Weh[L_*DH_];
__device__ __align__(16) __half g_R[(size_t)BH_*L_*L_ + 128]; // bias (log2 domain), padded

// ---------------------------------------------------------------------------
// helpers
// ---------------------------------------------------------------------------
__device__ __forceinline__ void mma16h(float* c,
    unsigned a0, unsigned a1, unsigned a2, unsigned a3,
    unsigned b0, unsigned b1)
{
    asm volatile(
        "mma.sync.aligned.m16n8k16.row.col.f32.f16.f16.f32 "
        "{%0,%1,%2,%3},{%4,%5,%6,%7},{%8,%9},{%0,%1,%2,%3};"
        : "+f"(c[0]), "+f"(c[1]), "+f"(c[2]), "+f"(c[3])
        : "r"(a0), "r"(a1), "r"(a2), "r"(a3), "r"(b0), "r"(b1));
}
__device__ __forceinline__ void ldsm4(unsigned& r0, unsigned& r1,
                                      unsigned& r2, unsigned& r3, unsigned addr)
{
    asm volatile("ldmatrix.sync.aligned.m8n8.x4.shared.b16 {%0,%1,%2,%3}, [%4];"
        : "=r"(r0), "=r"(r1), "=r"(r2), "=r"(r3) : "r"(addr));
}
__device__ __forceinline__ void ldsm4t(unsigned& r0, unsigned& r1,
                                       unsigned& r2, unsigned& r3, unsigned addr)
{
    asm volatile("ldmatrix.sync.aligned.m8n8.x4.trans.shared.b16 {%0,%1,%2,%3}, [%4];"
        : "=r"(r0), "=r"(r1), "=r"(r2), "=r"(r3) : "r"(addr));
}
__device__ __forceinline__ unsigned ex2h2(float lo, float hi) {
    unsigned p;
    asm("cvt.rn.f16x2.f32 %0, %1, %2;" : "=r"(p) : "f"(hi), "f"(lo));
    asm("ex2.approx.f16x2 %0, %0;" : "+r"(p));
    return p;
}
__device__ __forceinline__ unsigned scvta(const void* p) {
    return (unsigned)__cvta_generic_to_shared(p);
}
__device__ __forceinline__ void cpa16(unsigned dst, const void* src) {
    asm volatile("cp.async.cg.shared.global [%0], [%1], 16;" :: "r"(dst), "l"(src));
}
__device__ __forceinline__ void cpa_commit() {
    asm volatile("cp.async.commit_group;");
}
template<int N> __device__ __forceinline__ void cpa_wait() {
    asm volatile("cp.async.wait_group %0;" :: "n"(N));
}

// ---------------------------------------------------------------------------
// Prep: ONE launch converting all inputs to fp16
// ---------------------------------------------------------------------------
#define XN_ (M_*D_)
#define WN_ (D_*D_)
__global__ void __launch_bounds__(256) prep_kernel(
    const float* __restrict__ x,  const float* __restrict__ Wq,
    const float* __restrict__ Wk, const float* __restrict__ Wv,
    const float* __restrict__ Wo, const float* __restrict__ We)
{
    int i = (blockIdx.x * 256 + threadIdx.x) * 4;
    if (i >= XN_ + 4*WN_ + L_*DH_) return;
    const float* s; __half* d;
    if      (i < XN_)          { s = x  + i;               d = g_xh  + i; }
    else if (i < XN_ + WN_)    { s = Wq + i - XN_;         d = g_Wqh + i - XN_; }
    else if (i < XN_ + 2*WN_)  { s = Wk + i - XN_ - WN_;   d = g_Wkh + i - XN_ - WN_; }
    else if (i < XN_ + 3*WN_)  { s = Wv + i - XN_ - 2*WN_; d = g_Wvh + i - XN_ - 2*WN_; }
    else if (i < XN_ + 4*WN_)  { s = Wo + i - XN_ - 3*WN_; d = g_Woh + i - XN_ - 3*WN_; }
    else                       { s = We + i - XN_ - 4*WN_; d = g_Weh + i - XN_ - 4*WN_; }
    float4 v = *(const float4*)s;
    *(__half2*)(d)     = __floats2half2_rn(v.x, v.y);
    *(__half2*)(d + 2) = __floats2half2_rn(v.z, v.w);
}

// ---------------------------------------------------------------------------
// Dense fp16 GEMM body (K=512): C(128x128) = A * W^T, fp32 accum.
// 3-stage cp.async, ldmatrix frags, pitch 40 halves (conflict-free).
// ---------------------------------------------------------------------------
__device__ __forceinline__ void gemm_body_h(
    const __half* __restrict__ A, const __half* __restrict__ W,
    int mBase, int nBase, __half* As, __half* Bs, float C[2][8][4])
{
    const int t = threadIdx.x, lane = t & 31, warp = t >> 5;
    const int wm = warp >> 1, wn = warp & 1;
    const int srow = t >> 1, sc = (t & 1) * 2;
    const int BUF = 128 * 40;

    unsigned a_a = scvta(As) + (unsigned)(srow * 80);
    unsigned b_a = scvta(Bs) + (unsigned)(srow * 80);

    auto stage = [&](int buf, int k0) {
        unsigned off = (unsigned)(buf * BUF * 2);
        #pragma unroll
        for (int i = 0; i < 2; i++) {
            int ci = sc + i;
            cpa16(a_a + off + ci*16, A + (size_t)(mBase + srow) * D_ + k0 + ci*8);
            cpa16(b_a + off + ci*16, W + (size_t)(nBase + srow) * D_ + k0 + ci*8);
        }
        cpa_commit();
    };

    const int lr8 = lane & 7;
    unsigned aAddr = scvta(As) +
        (unsigned)(((wm*32 + (lane & 15))*40 + (lane >> 4)*8) * 2);
    unsigned bAddr = scvta(Bs) +
        (unsigned)(((wn*64 + lr8 + ((lane & 16) ? 8 : 0))*40 + ((lane & 8) ? 8 : 0)) * 2);

    stage(0, 0);
    stage(1, 32);
    int cb = 0, nb = 2, nk = 64;
    for (int it = 0; it < 16; it++) {
        if (it == 15) cpa_wait<0>(); else cpa_wait<1>();
        __syncthreads();
        if (it + 2 < 16) {
            stage(nb, nk);
            nk += 32;
            nb = (nb == 2) ? 0 : nb + 1;
        }
        const unsigned bo = (unsigned)(cb * BUF * 2);
        #pragma unroll
        for (int kk = 0; kk < 32; kk += 16) {
            unsigned a[2][4];
            #pragma unroll
            for (int mi = 0; mi < 2; mi++)
                ldsm4(a[mi][0], a[mi][1], a[mi][2], a[mi][3],
                      aAddr + bo + (unsigned)((mi*16*40 + kk) * 2));
            #pragma unroll
            for (int jp = 0; jp < 4; jp++) {
                unsigned b0, b1, b2, b3;
                ldsm4(b0, b1, b2, b3, bAddr + bo + (unsigned)((jp*16*40 + kk) * 2));
                mma16h(C[0][jp*2],   a[0][0], a[0][1], a[0][2], a[0][3], b0, b1);
                mma16h(C[0][jp*2+1], a[0][0], a[0][1], a[0][2], a[0][3], b2, b3);
                mma16h(C[1][jp*2],   a[1][0], a[1][1], a[1][2], a[1][3], b0, b1);
                mma16h(C[1][jp*2+1], a[1][0], a[1][1], a[1][2], a[1][3], b2, b3);
            }
        }
        cb = (cb == 2) ? 0 : cb + 1;
    }
}

// ---------------------------------------------------------------------------
// Kernel: QKV projections -> fp16 (b,h,l,dh). Q scaled by 0.125*log2(e).
// ---------------------------------------------------------------------------
__global__ void __launch_bounds__(256, 2) qkv_kernel()
{
    extern __shared__ __half smqh[];
    __half* As = smqh;
    __half* Bs = smqh + 3*128*40;
    const __half* W = (blockIdx.z == 0) ? g_Wqh : (blockIdx.z == 1) ? g_Wkh : g_Wvh;
    __half* dst     = (blockIdx.z == 0) ? g_Qh  : (blockIdx.z == 1) ? g_Kh  : g_Vh;
    const float scale = (blockIdx.z == 0) ? 0.125f * 1.4426950408889634f : 1.0f;
    const int mBase = blockIdx.x * 128, nBase = blockIdx.y * 128;
    float C[2][8][4] = {};
    gemm_body_h(g_xh, W, mBase, nBase, As, Bs, C);

    const int t = threadIdx.x, lane = t & 31, warp = t >> 5;
    const int g = lane >> 2, tg = lane & 3;
    const int wm = warp >> 1, wn = warp & 1;
    #pragma unroll
    for (int mi = 0; mi < 2; mi++) {
        #pragma unroll
        for (int j = 0; j < 8; j++) {
            int n = nBase + wn*64 + j*8 + 2*tg;
            int h = n >> 6, dh = n & 63;
            #pragma unroll
            for (int hh = 0; hh < 2; hh++) {
                int m = mBase + wm*32 + mi*16 + g + 8*hh;
                int b = m >> 10, l = m & (L_-1);
                __half2 v = __floats2half2_rn(C[mi][j][hh*2]*scale, C[mi][j][hh*2+1]*scale);
                *(__half2*)(dst + ((size_t)((b*H_+h)*L_ + l))*DH_ + dh) = v;
            }
        }
    }
}

// ---------------------------------------------------------------------------
// Kernel: R[bh][l][e] = Qh[bh,l,:].Weh[e,:] (fp16 mma, K=64), fp16 output.
// Tiles whose full e-range is never gathered by attention are skipped:
// attention needs e >= 1023 - max(m, 1023-m) only.
// ---------------------------------------------------------------------------
__global__ void __launch_bounds__(256, 2) rel_kernel()
{
    const int mBase = blockIdx.x * 128, nBase = blockIdx.y * 128;
    {   // dead-tile early exit
        int Mmax = 1023 - mBase;
        if (mBase + 127 > Mmax) Mmax = mBase + 127;
        if (nBase < 896 - Mmax) return;
    }

    extern __shared__ __half smr[];
    __half* Ah = smr;               // 128 x 72 halves
    __half* Bh = smr + 128*72;
    const int bh = blockIdx.z;
    const __half* A  = g_Qh + (size_t)bh * L_ * DH_;
    const __half* Wb = g_Weh;

    const int t = threadIdx.x, lane = t & 31, warp = t >> 5;
    const int wm = warp >> 1, wn = warp & 1;

    const int lr2 = t >> 1, lc2 = (t & 1) * 4;
    unsigned a_a = scvta(Ah) + (unsigned)(lr2*144);
    unsigned b_a = scvta(Bh) + (unsigned)(lr2*144);
    #pragma unroll
    for (int i = 0; i < 4; i++) {
        int ci = lc2 + i;
        cpa16(a_a + ci*16, A  + (size_t)(mBase + lr2) * DH_ + ci*8);
        cpa16(b_a + ci*16, Wb + (size_t)(nBase + lr2) * DH_ + ci*8);
    }
    cpa_commit(); cpa_wait<0>();
    __syncthreads();

    const int lr8 = lane & 7;
    unsigned aAddr = scvta(Ah) +
        (unsigned)(((wm*32 + (lane & 15))*72 + ((lane >> 4)*8)) * 2);
    unsigned bAddr = scvta(Bh) +
        (unsigned)(((wn*64 + lr8 + ((lane & 16) ? 8 : 0))*72 + ((lane & 8) ? 8 : 0)) * 2);

    float C[2][8][4] = {};
    #pragma unroll
    for (int k0 = 0; k0 < 64; k0 += 16) {
        unsigned a[2][4];
        #pragma unroll
        for (int mi = 0; mi < 2; mi++)
            ldsm4(a[mi][0], a[mi][1], a[mi][2], a[mi][3],
                  aAddr + (unsigned)((mi*16*72 + k0) * 2));
        #pragma unroll
        for (int jp = 0; jp < 4; jp++) {
            unsigned b0, b1, b2, b3;
            ldsm4(b0, b1, b2, b3, bAddr + (unsigned)((jp*16*72 + k0) * 2));
            mma16h(C[0][jp*2],   a[0][0], a[0][1], a[0][2], a[0][3], b0, b1);
            mma16h(C[0][jp*2+1], a[0][0], a[0][1], a[0][2], a[0][3], b2, b3);
            mma16h(C[1][jp*2],   a[1][0], a[1][1], a[1][2], a[1][3], b0, b1);
            mma16h(C[1][jp*2+1], a[1][0], a[1][1], a[1][2], a[1][3], b2, b3);
        }
    }

    const int g = lane >> 2, tg = lane & 3;
    __half* Rb = g_R + (size_t)bh * L_ * L_;
    #pragma unroll
    for (int mi = 0; mi < 2; mi++) {
        #pragma unroll
        for (int j = 0; j < 8; j++) {
            int n = nBase + wn*64 + j*8 + 2*tg;
            #pragma unroll
            for (int hh = 0; hh < 2; hh++) {
                int m = mBase + wm*32 + mi*16 + g + 8*hh;
                __half2 v = __floats2half2_rn(C[mi][j][hh*2], C[mi][j][hh*2+1]);
                *(__half2*)(Rb + (size_t)m*L_ + n) = v;
            }
        }
    }
}

// ---------------------------------------------------------------------------
// Kernel: flash attention. 256 threads, 128-row q-tiles, double-buffered
// K/V/bias staging, all-fp16 mma. Bias windows at pitch 88 halves
// (bank = (12g+tg) mod 32, fully conflict-free gather LDS).
// ---------------------------------------------------------------------------
__global__ void __launch_bounds__(256, 2) attn_kernel()
{
    extern __shared__ __half sma[];
    __half* Qh = sma;                    // 128 x 72
    __half* Kh = Qh + 128*72;            // 2 buf x 64 x 72
    __half* Vh = Kh + 2*64*72;           // 2 buf x 64 x 72
    __half* Rw = Vh + 2*64*72;           // 2 buf x 128 x 88

    const int KVB = 64*72;
    const int RWB = 128*88;

    const int bh = blockIdx.y, lBase = blockIdx.x * 128;
    const __half* __restrict__ Qg = g_Qh + (size_t)bh * L_ * DH_;
    const __half* __restrict__ Kg = g_Kh + (size_t)bh * L_ * DH_;
    const __half* __restrict__ Vg = g_Vh + (size_t)bh * L_ * DH_;
    const __half* __restrict__ Rg = g_R + ((size_t)bh << 20);

    const int t = threadIdx.x, lane = t & 31, warp = t >> 5;
    const int g = lane >> 2, tg = lane & 3;
    const int rA = warp*16 + g;          // 0..127

    const int qrow = t >> 1, qcb = (t & 1) * 4;
    const int krow = t & 63, kcb = (t >> 6) * 2;
    const int rrow = t >> 1, rcb = (t & 1) * 5;
    unsigned q_a = scvta(Qh) + (unsigned)(qrow*144);
    unsigned k_a = scvta(Kh) + (unsigned)(krow*144);
    unsigned v_a = scvta(Vh) + (unsigned)(krow*144);
    unsigned r_a = scvta(Rw) + (unsigned)(rrow*176);
    const int rl = lBase + rrow;
    const __half* Rrow = Rg + ((size_t)rl << 10);

    auto admax = [](int l, int sB) {
        int a0 = l - sB;      if (a0 < 0) a0 = -a0;
        int a1 = l - sB - 63; if (a1 < 0) a1 = -a1;
        return a0 > a1 ? a0 : a1;
    };

    auto stage_kvr = [&](int buf, int sB) {
        unsigned kvoff = (unsigned)(buf * KVB * 2);
        unsigned rwoff = (unsigned)(buf * RWB * 2);
        #pragma unroll
        for (int i = 0; i < 2; i++) {
            int ci = kcb + i;
            cpa16(k_a + kvoff + ci*16, Kg + (size_t)(sB + krow)*DH_ + ci*8);
            cpa16(v_a + kvoff + ci*16, Vg + (size_t)(sB + krow)*DH_ + ci*8);
        }
        int e_lo8 = (1023 - admax(rl, sB)) & ~7;
        #pragma unroll
        for (int i = 0; i < 5; i++) {
            int ci = rcb + i;
            cpa16(r_a + rwoff + (unsigned)(ci*16), Rrow + e_lo8 + ci*8);
        }
        cpa_commit();
    };

    {   // stage Q (once) + tile 0 into buffer 0
        #pragma unroll
        for (int i = 0; i < 4; i++) {
            int ci = qcb + i;
            cpa16(q_a + ci*16, Qg + (size_t)(lBase + qrow)*DH_ + ci*8);
        }
        stage_kvr(0, 0);
    }

    const int lr8 = lane & 7;
    unsigned aQ = scvta(Qh) +
        (unsigned)(((warp*16 + (lane & 15))*72 + ((lane >> 4)*8)) * 2);
    unsigned bK0 = scvta(Kh) +
        (unsigned)(((lr8 + ((lane & 16) ? 8 : 0))*72 + ((lane & 8) ? 8 : 0)) * 2);
    unsigned bV0 = scvta(Vh) +
        (unsigned)(((lane & 15)*72 + (lane >> 4)*8) * 2);

    const unsigned ONES = 0x3C003C00u;
    float lsum[4] = {0.f, 0.f, 0.f, 0.f};
    float O[8][4] = {};

    const int lg0 = lBase + rA, lg1 = lg0 + 8;

    for (int it = 0; it < 16; it++) {
        const int sBase = it * 64;
        const int buf = it & 1;

        cpa_wait<0>();
        __syncthreads();                                    // tile `it` staged

        if (it + 1 < 16)                                    // overlap: stage i+1
            stage_kvr(buf ^ 1, sBase + 64);

        const unsigned kvoff = (unsigned)(buf * KVB * 2);
        const __half* Rb = Rw + buf * RWB;

        // ---- sf init: bias gather from staged windows (conflict-free) ----
        float sf[8][4];
        if (lBase >= sBase + 64) {
            const __half* p0 = Rb + rA*88     + ((1023 - lg0 + sBase) & 7) + 2*tg;
            const __half* p1 = Rb + (rA+8)*88 + ((1023 - lg1 + sBase) & 7) + 2*tg;
            #pragma unroll
            for (int j = 0; j < 8; j++) {
                sf[j][0] = __half2float(p0[j*8]);
                sf[j][1] = __half2float(p0[j*8 + 1]);
                sf[j][2] = __half2float(p1[j*8]);
                sf[j][3] = __half2float(p1[j*8 + 1]);
            }
        } else if (sBase >= lBase + 128) {
            const __half* p0 = Rb + rA*88     + ((960 - sBase + lg0) & 7) + 63 - 2*tg;
            const __half* p1 = Rb + (rA+8)*88 + ((960 - sBase + lg1) & 7) + 63 - 2*tg;
            #pragma unroll
            for (int j = 0; j < 8; j++) {
                sf[j][0] = __half2float(p0[-(j*8)]);
                sf[j][1] = __half2float(p0[-(j*8) - 1]);
                sf[j][2] = __half2float(p1[-(j*8)]);
                sf[j][3] = __half2float(p1[-(j*8) - 1]);
            }
        } else {
            const int base0 = 1023 - ((1023 - admax(lg0, sBase)) & ~7);
            const int base1 = 1023 - ((1023 - admax(lg1, sBase)) & ~7);
            #pragma unroll
            for (int j = 0; j < 8; j++) {
                int c0 = sBase + j*8 + 2*tg;
                #pragma unroll
                for (int q = 0; q < 4; q++) {
                    int col  = c0 + (q & 1);
                    int lg   = (q < 2) ? lg0 : lg1;
                    int rloc = (q < 2) ? rA  : rA + 8;
                    int base = (q < 2) ? base0 : base1;
                    int d = lg - col; int ad = d < 0 ? -d : d;
                    sf[j][q] = __half2float(Rb[rloc*88 + base - ad]);
                }
            }
        }

        // ---- S GEMM (fp16, accumulates onto bias) ----
        #pragma unroll
        for (int k0 = 0; k0 < 64; k0 += 16) {
            unsigned a0, a1, a2, a3;
            ldsm4(a0, a1, a2, a3, aQ + (unsigned)(k0*2));
            #pragma unroll
            for (int jp = 0; jp < 4; jp++) {
                unsigned b0, b1, b2, b3;
                ldsm4(b0, b1, b2, b3, bK0 + kvoff + (unsigned)((jp*16*72 + k0) * 2));
                mma16h(sf[jp*2],   a0, a1, a2, a3, b0, b1);
                mma16h(sf[jp*2+1], a0, a1, a2, a3, b2, b3);
            }
        }

        // ---- fp16 softmax tail + PV ----
        #pragma unroll
        for (int j2 = 0; j2 < 4; j2++) {
            const int jb0 = 2*j2, jb1 = 2*j2 + 1;
            unsigned a0 = ex2h2(sf[jb0][0], sf[jb0][1]);
            unsigned a1 = ex2h2(sf[jb0][2], sf[jb0][3]);
            unsigned a2 = ex2h2(sf[jb1][0], sf[jb1][1]);
            unsigned a3 = ex2h2(sf[jb1][2], sf[jb1][3]);
            mma16h(lsum, a0, a1, a2, a3, ONES, ONES);
            #pragma unroll
            for (int jp = 0; jp < 4; jp++) {
                unsigned b0, b1, b2, b3;
                ldsm4t(b0, b1, b2, b3, bV0 + kvoff + (unsigned)((j2*16*72 + jp*16) * 2));
                mma16h(O[jp*2],   a0, a1, a2, a3, b0, b1);
                mma16h(O[jp*2+1], a0, a1, a2, a3, b2, b3);
            }
        }
        // buffer reuse protected by next iteration's top sync
    }

    // normalize + write ctx (fp16)
    const float i0 = 1.0f / lsum[0], i1 = 1.0f / lsum[2];
    const int b = bh >> 3, hh = bh & 7;
    #pragma unroll
    for (int j = 0; j < 8; j++) {
        int dh = j*8 + 2*tg;
        size_t base0 = ((size_t)(b*L_ + lBase + rA))*D_ + hh*DH_ + dh;
        size_t base1 = ((size_t)(b*L_ + lBase + rA + 8))*D_ + hh*DH_ + dh;
        *(__half2*)(g_Ctxh + base0) = __floats2half2_rn(O[j][0]*i0, O[j][1]*i0);
        *(__half2*)(g_Ctxh + base1) = __floats2half2_rn(O[j][2]*i1, O[j][3]*i1);
    }
}

// ---------------------------------------------------------------------------
// Kernel: out = Ctx @ Wo^T + bo   (fp16 GEMM, fp32 out)
// ---------------------------------------------------------------------------
__global__ void __launch_bounds__(256, 2) out_kernel(
    const float* __restrict__ bo, float* __restrict__ out)
{
    extern __shared__ __half smqh[];
    __half* As = smqh;
    __half* Bs = smqh + 3*128*40;
    const int mBase = blockIdx.x * 128, nBase = blockIdx.y * 128;
    float C[2][8][4] = {};
    gemm_body_h(g_Ctxh, g_Woh, mBase, nBase, As, Bs, C);

    const int t = threadIdx.x, lane = t & 31, warp = t >> 5;
    const int g = lane >> 2, tg = lane & 3;
    const int wm = warp >> 1, wn = warp & 1;
    #pragma unroll
    for (int mi = 0; mi < 2; mi++) {
        #pragma unroll
        for (int j = 0; j < 8; j++) {
            int n = nBase + wn*64 + j*8 + 2*tg;
            float2 bias = *(const float2*)(bo + n);
            #pragma unroll
            for (int hh = 0; hh < 2; hh++) {
                int m = mBase + wm*32 + mi*16 + g + 8*hh;
                float2 v = make_float2(C[mi][j][hh*2] + bias.x, C[mi][j][hh*2+1] + bias.y);
                *(float2*)(out + (size_t)m*D_ + n) = v;
            }
        }
    }
}

// ---------------------------------------------------------------------------
extern "C" void kernel_launch(void* const* d_in, const int* in_sizes, int n_in,
                              void* d_out, int out_size)
{
    const float* x  = (const float*)d_in[0];
    const float* Wq = (const float*)d_in[1];
    const float* Wk = (const float*)d_in[2];
    const float* Wv = (const float*)d_in[3];
    const float* We = (const float*)d_in[4];
    const float* Wo = (const float*)d_in[5];
    const float* bo = (const float*)d_in[6];
    float* out = (float*)d_out;

    const int gemm_smem = 2 * 3 * 128 * 40 * (int)sizeof(__half);        // 61440
    const int rel_smem  = 2 * 128 * 72 * (int)sizeof(__half);            // 36864
    const int attn_smem = (128*72 + 2*64*72 + 2*64*72 + 2*128*88)
                          * (int)sizeof(__half);                         // 100352
    cudaFuncSetAttribute(qkv_kernel,  cudaFuncAttributeMaxDynamicSharedMemorySize, gemm_smem);
    cudaFuncSetAttribute(rel_kernel,  cudaFuncAttributeMaxDynamicSharedMemorySize, rel_smem);
    cudaFuncSetAttribute(attn_kernel, cudaFuncAttributeMaxDynamicSharedMemorySize, attn_smem);
    cudaFuncSetAttribute(out_kernel,  cudaFuncAttributeMaxDynamicSharedMemorySize, gemm_smem);

    const int prep_total = XN_ + 4*WN_ + L_*DH_;
    prep_kernel<<<(prep_total/4 + 255)/256, 256>>>(x, Wq, Wk, Wv, Wo, We);

    qkv_kernel<<<dim3(M_/128, D_/128, 3), 256, gemm_smem>>>();
    rel_kernel<<<dim3(L_/128, L_/128, BH_), 256, rel_smem>>>();
    attn_kernel<<<dim3(L_/128, BH_), 256, attn_smem>>>();
    out_kernel<<<dim3(M_/128, D_/128), 256, gemm_smem>>>(bo, out);
}

// round 16
// speedup vs baseline: 1.4380x; 1.3516x over previous
#include <cuda_runtime.h>
#include <cuda_fp16.h>
#include <math.h>

#define B_  8
#define L_  1024
#define D_  512
#define H_  8
#define DH_ 64
#define M_  (B_*L_)     // 8192
#define BH_ (B_*H_)     // 64

// Scratch (device globals: allocation-free kernel_launch per harness rules)
__device__ __align__(16) __half g_Qh[BH_*L_*DH_];  // fp16, 0.125*log2e-scaled
__device__ __align__(16) __half g_Kh[BH_*L_*DH_];
__device__ __align__(16) __half g_Vh[BH_*L_*DH_];
__device__ __align__(16) __half g_Ctxh[M_*D_];     // fp16, (b,l,D)
__device__ __align__(16) __half g_xh[M_*D_];       // fp16 inputs
__device__ __align__(16) __half g_Wqh[D_*D_];
__device__ __align__(16) __half g_Wkh[D_*D_];
__device__ __align__(16) __half g_Wvh[D_*D_];
__device__ __align__(16) __half g_Woh[D_*D_];
__device__ __align__(16) __half g_Weh[L_*DH_];

// ---------------------------------------------------------------------------
// helpers
// ---------------------------------------------------------------------------
__device__ __forceinline__ void mma16h(float* c,
    unsigned a0, unsigned a1, unsigned a2, unsigned a3,
    unsigned b0, unsigned b1)
{
    asm volatile(
        "mma.sync.aligned.m16n8k16.row.col.f32.f16.f16.f32 "
        "{%0,%1,%2,%3},{%4,%5,%6,%7},{%8,%9},{%0,%1,%2,%3};"
        : "+f"(c[0]), "+f"(c[1]), "+f"(c[2]), "+f"(c[3])
        : "r"(a0), "r"(a1), "r"(a2), "r"(a3), "r"(b0), "r"(b1));
}
__device__ __forceinline__ void ldsm4(unsigned& r0, unsigned& r1,
                                      unsigned& r2, unsigned& r3, unsigned addr)
{
    asm volatile("ldmatrix.sync.aligned.m8n8.x4.shared.b16 {%0,%1,%2,%3}, [%4];"
        : "=r"(r0), "=r"(r1), "=r"(r2), "=r"(r3) : "r"(addr));
}
__device__ __forceinline__ void ldsm4t(unsigned& r0, unsigned& r1,
                                       unsigned& r2, unsigned& r3, unsigned addr)
{
    asm volatile("ldmatrix.sync.aligned.m8n8.x4.trans.shared.b16 {%0,%1,%2,%3}, [%4];"
        : "=r"(r0), "=r"(r1), "=r"(r2), "=r"(r3) : "r"(addr));
}
__device__ __forceinline__ unsigned ex2h2(float lo, float hi) {
    unsigned p;
    asm("cvt.rn.f16x2.f32 %0, %1, %2;" : "=r"(p) : "f"(hi), "f"(lo));
    asm("ex2.approx.f16x2 %0, %0;" : "+r"(p));
    return p;
}
__device__ __forceinline__ unsigned scvta(const void* p) {
    return (unsigned)__cvta_generic_to_shared(p);
}
__device__ __forceinline__ void cpa16(unsigned dst, const void* src) {
    asm volatile("cp.async.cg.shared.global [%0], [%1], 16;" :: "r"(dst), "l"(src));
}
__device__ __forceinline__ void cpa_commit() {
    asm volatile("cp.async.commit_group;");
}
template<int N> __device__ __forceinline__ void cpa_wait() {
    asm volatile("cp.async.wait_group %0;" :: "n"(N));
}

// ---------------------------------------------------------------------------
// Prep: ONE launch converting all inputs to fp16
// ---------------------------------------------------------------------------
#define XN_ (M_*D_)
#define WN_ (D_*D_)
__global__ void __launch_bounds__(256) prep_kernel(
    const float* __restrict__ x,  const float* __restrict__ Wq,
    const float* __restrict__ Wk, const float* __restrict__ Wv,
    const float* __restrict__ Wo, const float* __restrict__ We)
{
    int i = (blockIdx.x * 256 + threadIdx.x) * 4;
    if (i >= XN_ + 4*WN_ + L_*DH_) return;
    const float* s; __half* d;
    if      (i < XN_)          { s = x  + i;               d = g_xh  + i; }
    else if (i < XN_ + WN_)    { s = Wq + i - XN_;         d = g_Wqh + i - XN_; }
    else if (i < XN_ + 2*WN_)  { s = Wk + i - XN_ - WN_;   d = g_Wkh + i - XN_ - WN_; }
    else if (i < XN_ + 3*WN_)  { s = Wv + i - XN_ - 2*WN_; d = g_Wvh + i - XN_ - 2*WN_; }
    else if (i < XN_ + 4*WN_)  { s = Wo + i - XN_ - 3*WN_; d = g_Woh + i - XN_ - 3*WN_; }
    else                       { s = We + i - XN_ - 4*WN_; d = g_Weh + i - XN_ - 4*WN_; }
    float4 v = *(const float4*)s;
    *(__half2*)(d)     = __floats2half2_rn(v.x, v.y);
    *(__half2*)(d + 2) = __floats2half2_rn(v.z, v.w);
}

// ---------------------------------------------------------------------------
// Dense fp16 GEMM body (K=512): C(128x128) = A * W^T, fp32 accum.
// ---------------------------------------------------------------------------
__device__ __forceinline__ void gemm_body_h(
    const __half* __restrict__ A, const __half* __restrict__ W,
    int mBase, int nBase, __half* As, __half* Bs, float C[2][8][4])
{
    const int t = threadIdx.x, lane = t & 31, warp = t >> 5;
    const int wm = warp >> 1, wn = warp & 1;
    const int srow = t >> 1, sc = (t & 1) * 2;
    const int BUF = 128 * 40;

    unsigned a_a = scvta(As) + (unsigned)(srow * 80);
    unsigned b_a = scvta(Bs) + (unsigned)(srow * 80);

    auto stage = [&](int buf, int k0) {
        unsigned off = (unsigned)(buf * BUF * 2);
        #pragma unroll
        for (int i = 0; i < 2; i++) {
            int ci = sc + i;
            cpa16(a_a + off + ci*16, A + (size_t)(mBase + srow) * D_ + k0 + ci*8);
            cpa16(b_a + off + ci*16, W + (size_t)(nBase + srow) * D_ + k0 + ci*8);
        }
        cpa_commit();
    };

    const int lr8 = lane & 7;
    unsigned aAddr = scvta(As) +
        (unsigned)(((wm*32 + (lane & 15))*40 + (lane >> 4)*8) * 2);
    unsigned bAddr = scvta(Bs) +
        (unsigned)(((wn*64 + lr8 + ((lane & 16) ? 8 : 0))*40 + ((lane & 8) ? 8 : 0)) * 2);

    stage(0, 0);
    stage(1, 32);
    int cb = 0, nb = 2, nk = 64;
    for (int it = 0; it < 16; it++) {
        if (it == 15) cpa_wait<0>(); else cpa_wait<1>();
        __syncthreads();
        if (it + 2 < 16) {
            stage(nb, nk);
            nk += 32;
            nb = (nb == 2) ? 0 : nb + 1;
        }
        const unsigned bo = (unsigned)(cb * BUF * 2);
        #pragma unroll
        for (int kk = 0; kk < 32; kk += 16) {
            unsigned a[2][4];
            #pragma unroll
            for (int mi = 0; mi < 2; mi++)
                ldsm4(a[mi][0], a[mi][1], a[mi][2], a[mi][3],
                      aAddr + bo + (unsigned)((mi*16*40 + kk) * 2));
            #pragma unroll
            for (int jp = 0; jp < 4; jp++) {
                unsigned b0, b1, b2, b3;
                ldsm4(b0, b1, b2, b3, bAddr + bo + (unsigned)((jp*16*40 + kk) * 2));
                mma16h(C[0][jp*2],   a[0][0], a[0][1], a[0][2], a[0][3], b0, b1);
                mma16h(C[0][jp*2+1], a[0][0], a[0][1], a[0][2], a[0][3], b2, b3);
                mma16h(C[1][jp*2],   a[1][0], a[1][1], a[1][2], a[1][3], b0, b1);
                mma16h(C[1][jp*2+1], a[1][0], a[1][1], a[1][2], a[1][3], b2, b3);
            }
        }
        cb = (cb == 2) ? 0 : cb + 1;
    }
}

// ---------------------------------------------------------------------------
// Kernel: QKV projections -> fp16 (b,h,l,dh). Q scaled by 0.125*log2(e).
// ---------------------------------------------------------------------------
__global__ void __launch_bounds__(256, 2) qkv_kernel()
{
    extern __shared__ __half smqh[];
    __half* As = smqh;
    __half* Bs = smqh + 3*128*40;
    const __half* W = (blockIdx.z == 0) ? g_Wqh : (blockIdx.z == 1) ? g_Wkh : g_Wvh;
    __half* dst     = (blockIdx.z == 0) ? g_Qh  : (blockIdx.z == 1) ? g_Kh  : g_Vh;
    const float scale = (blockIdx.z == 0) ? 0.125f * 1.4426950408889634f : 1.0f;
    const int mBase = blockIdx.x * 128, nBase = blockIdx.y * 128;
    float C[2][8][4] = {};
    gemm_body_h(g_xh, W, mBase, nBase, As, Bs, C);

    const int t = threadIdx.x, lane = t & 31, warp = t >> 5;
    const int g = lane >> 2, tg = lane & 3;
    const int wm = warp >> 1, wn = warp & 1;
    #pragma unroll
    for (int mi = 0; mi < 2; mi++) {
        #pragma unroll
        for (int j = 0; j < 8; j++) {
            int n = nBase + wn*64 + j*8 + 2*tg;
            int h = n >> 6, dh = n & 63;
            #pragma unroll
            for (int hh = 0; hh < 2; hh++) {
                int m = mBase + wm*32 + mi*16 + g + 8*hh;
                int b = m >> 10, l = m & (L_-1);
                __half2 v = __floats2half2_rn(C[mi][j][hh*2]*scale, C[mi][j][hh*2+1]*scale);
                *(__half2*)(dst + ((size_t)((b*H_+h)*L_ + l))*DH_ + dh) = v;
            }
        }
    }
}

// ---------------------------------------------------------------------------
// Kernel: flash attention with on-the-fly bias GEMM + parity-slot cache.
// 128 threads, 64-row q-tiles. Bias window per 64-wide s-tile = exactly 2
// aligned 64-blocks {b0,b0+1}, b0 = min(14, 15-|it-lq|); consecutive tiles
// share one -> <=1 new T GEMM (Qfrag x We-block) per tile, warp-private rows.
// Cache addressing: Tc[row][idx & 127] (slot = block parity). No R matrix,
// no rel kernel, ~zero bias DRAM traffic.
// ---------------------------------------------------------------------------
__global__ void __launch_bounds__(128, 3) attn_kernel()
{
    extern __shared__ __half sma[];
    __half* Tc = sma;                   // 64 x 152 halves (first 4608 h = Q staging)
    __half* Kh = sma + 9728;            // 2 x 64 x 72
    __half* Vh = Kh + 2*4608;           // 2 x 64 x 72
    __half* Ws = Vh + 2*4608;           // 2 x 64 x 72 (We blocks)

    const int bh = blockIdx.y, lq = blockIdx.x, lBase = lq * 64;
    const __half* __restrict__ Qg = g_Qh + (size_t)bh * L_ * DH_;
    const __half* __restrict__ Kg = g_Kh + (size_t)bh * L_ * DH_;
    const __half* __restrict__ Vg = g_Vh + (size_t)bh * L_ * DH_;
    const __half* __restrict__ Wg = g_Weh;

    const int t = threadIdx.x, lane = t & 31, warp = t >> 5;
    const int g = lane >> 2, tg = lane & 3;
    const int rA = warp*16 + g;
    const int lg0 = lBase + rA, lg1 = lg0 + 8;

    // staging map: 64 rows x 128B; 2 threads/row, 4 chunks each
    const int srow = t >> 1, scb = (t & 1) * 4;
    unsigned q_a = scvta(Tc) + (unsigned)(srow*144);
    unsigned k_a = scvta(Kh) + (unsigned)(srow*144);
    unsigned v_a = scvta(Vh) + (unsigned)(srow*144);
    unsigned w_a = scvta(Ws) + (unsigned)(srow*144);

    auto b0of = [](int u) { int v = 15 - u; return v > 14 ? 14 : v; };
    const int b00 = b0of(lq);

    {   // prologue: stage Q + K/V tile0 + both initial We blocks
        #pragma unroll
        for (int i = 0; i < 4; i++) {
            int ci = scb + i;
            cpa16(q_a + ci*16, Qg + (size_t)(lBase + srow)*DH_ + ci*8);
            cpa16(k_a + ci*16, Kg + (size_t)srow*DH_ + ci*8);
            cpa16(v_a + ci*16, Vg + (size_t)srow*DH_ + ci*8);
            cpa16(w_a + ci*16,        Wg + (size_t)(b00*64 + srow)*DH_ + ci*8);
            cpa16(w_a + 9216 + ci*16, Wg + (size_t)((b00+1)*64 + srow)*DH_ + ci*8);
        }
        cpa_commit(); cpa_wait<0>();
        __syncthreads();
    }

    // Q A-frags -> registers (pitch 72 staging in Tc region)
    const int lr8 = lane & 7;
    unsigned aQ = scvta(Tc) +
        (unsigned)(((warp*16 + (lane & 15))*72 + ((lane >> 4)*8)) * 2);
    unsigned qf[4][4];
    #pragma unroll
    for (int ks = 0; ks < 4; ks++)
        ldsm4(qf[ks][0], qf[ks][1], qf[ks][2], qf[ks][3], aQ + (unsigned)(ks*32));
    __syncthreads();    // all warps extracted Q before Tc is overwritten

    const unsigned bFragOff =
        (unsigned)(((lr8 + ((lane & 16) ? 8 : 0))*72 + ((lane & 8) ? 8 : 0)) * 2);
    unsigned bK0 = scvta(Kh) + bFragOff;
    unsigned bW0 = scvta(Ws) + bFragOff;
    unsigned bV0 = scvta(Vh) +
        (unsigned)(((lane & 15)*72 + (lane >> 4)*8) * 2);

    // T GEMM: bias block blk from Ws[buf] -> Tc cols (blk&1)*64
    auto tgemm = [&](int buf, int blk) {
        float tf[8][4] = {};
        unsigned wb = bW0 + (unsigned)(buf*9216);
        #pragma unroll
        for (int ks = 0; ks < 4; ks++) {
            #pragma unroll
            for (int jp = 0; jp < 4; jp++) {
                unsigned b0, b1, b2, b3;
                ldsm4(b0, b1, b2, b3, wb + (unsigned)((jp*16*72 + ks*16) * 2));
                mma16h(tf[jp*2],   qf[ks][0], qf[ks][1], qf[ks][2], qf[ks][3], b0, b1);
                mma16h(tf[jp*2+1], qf[ks][0], qf[ks][1], qf[ks][2], qf[ks][3], b2, b3);
            }
        }
        const int cbase = (blk & 1)*64 + 2*tg;
        #pragma unroll
        for (int j = 0; j < 8; j++) {
            *(__half2*)&Tc[rA*152     + cbase + j*8] = __floats2half2_rn(tf[j][0], tf[j][1]);
            *(__half2*)&Tc[(rA+8)*152 + cbase + j*8] = __floats2half2_rn(tf[j][2], tf[j][3]);
        }
        __syncwarp();
    };

    auto stage_kv = [&](int buf, int sB) {
        unsigned off = (unsigned)(buf * 9216);
        #pragma unroll
        for (int i = 0; i < 4; i++) {
            int ci = scb + i;
            cpa16(k_a + off + ci*16, Kg + (size_t)(sB + srow)*DH_ + ci*8);
            cpa16(v_a + off + ci*16, Vg + (size_t)(sB + srow)*DH_ + ci*8);
        }
    };

    const unsigned ONES = 0x3C003C00u;
    float lsum[4] = {0.f, 0.f, 0.f, 0.f};
    float O[8][4] = {};
    int b0prev = b00;

    for (int it = 0; it < 16; it++) {
        const int sBase = it * 64;
        const int buf = it & 1;
        const int u  = (it > lq) ? it - lq : lq - it;
        const int b0c = b0of(u);

        if (it > 0) {
            cpa_wait<0>();
            __syncthreads();                      // tile data staged; buffers safe
        }

        if (it == 0) {
            // build both initial bias blocks, then sync before Ws[1] is re-staged
            tgemm(0, b00);
            tgemm(1, b00 + 1);
            __syncthreads();
        } else if (b0c != b0prev) {
            tgemm(buf, (b0c > b0prev) ? b0c + 1 : b0c);
            b0prev = b0c;
        }

        if (it + 1 < 16) {                        // prefetch next tile
            stage_kv(buf ^ 1, sBase + 64);
            const int un  = (it + 1 > lq) ? it + 1 - lq : lq - it - 1;
            const int b0n = b0of(un);
            if (b0n != b0c) {
                int nb = (b0n > b0c) ? b0n + 1 : b0n;
                unsigned off = (unsigned)((buf ^ 1) * 9216);
                #pragma unroll
                for (int i = 0; i < 4; i++) {
                    int ci = scb + i;
                    cpa16(w_a + off + ci*16, Wg + (size_t)(nb*64 + srow)*DH_ + ci*8);
                }
            }
            cpa_commit();
        }

        // ---- sf init: bias gather from cache Tc[row][idx & 127] ----
        float sf[8][4];
        #pragma unroll
        for (int j = 0; j < 8; j++) {
            int c0 = sBase + j*8 + 2*tg;
            #pragma unroll
            for (int q = 0; q < 4; q++) {
                int col = c0 + (q & 1);
                int lgv = (q < 2) ? lg0 : lg1;
                int row = (q < 2) ? rA  : rA + 8;
                int d = lgv - col; int ad = d < 0 ? -d : d;
                int idx = (L_ - 1) - ad;
                sf[j][q] = __half2float(Tc[row*152 + (idx & 127)]);
            }
        }

        // ---- S GEMM (fp16, Q-frags in regs, accumulates onto bias) ----
        const unsigned kvoff = (unsigned)(buf * 9216);
        #pragma unroll
        for (int ks = 0; ks < 4; ks++) {
            #pragma unroll
            for (int jp = 0; jp < 4; jp++) {
                unsigned b0, b1, b2, b3;
                ldsm4(b0, b1, b2, b3, bK0 + kvoff + (unsigned)((jp*16*72 + ks*16) * 2));
                mma16h(sf[jp*2],   qf[ks][0], qf[ks][1], qf[ks][2], qf[ks][3], b0, b1);
                mma16h(sf[jp*2+1], qf[ks][0], qf[ks][1], qf[ks][2], qf[ks][3], b2, b3);
            }
        }

        // ---- fp16 softmax tail + PV ----
        #pragma unroll
        for (int j2 = 0; j2 < 4; j2++) {
            const int jb0 = 2*j2, jb1 = 2*j2 + 1;
            unsigned a0 = ex2h2(sf[jb0][0], sf[jb0][1]);
            unsigned a1 = ex2h2(sf[jb0][2], sf[jb0][3]);
            unsigned a2 = ex2h2(sf[jb1][0], sf[jb1][1]);
            unsigned a3 = ex2h2(sf[jb1][2], sf[jb1][3]);
            mma16h(lsum, a0, a1, a2, a3, ONES, ONES);
            #pragma unroll
            for (int jp = 0; jp < 4; jp++) {
                unsigned b0, b1, b2, b3;
                ldsm4t(b0, b1, b2, b3, bV0 + kvoff + (unsigned)((j2*16*72 + jp*16) * 2));
                mma16h(O[jp*2],   a0, a1, a2, a3, b0, b1);
                mma16h(O[jp*2+1], a0, a1, a2, a3, b2, b3);
            }
        }
        // K/V/Ws buffer reuse protected by next iteration's top sync
    }

    // normalize + write ctx (fp16)
    const float i0 = 1.0f / lsum[0], i1 = 1.0f / lsum[2];
    const int b = bh >> 3, hh = bh & 7;
    #pragma unroll
    for (int j = 0; j < 8; j++) {
        int dh = j*8 + 2*tg;
        size_t base0 = ((size_t)(b*L_ + lg0))*D_ + hh*DH_ + dh;
        size_t base1 = ((size_t)(b*L_ + lg1))*D_ + hh*DH_ + dh;
        *(__half2*)(g_Ctxh + base0) = __floats2half2_rn(O[j][0]*i0, O[j][1]*i0);
        *(__half2*)(g_Ctxh + base1) = __floats2half2_rn(O[j][2]*i1, O[j][3]*i1);
    }
}

// ---------------------------------------------------------------------------
// Kernel: out = Ctx @ Wo^T + bo   (fp16 GEMM, fp32 out)
// ---------------------------------------------------------------------------
__global__ void __launch_bounds__(256, 2) out_kernel(
    const float* __restrict__ bo, float* __restrict__ out)
{
    extern __shared__ __half smqh[];
    __half* As = smqh;
    __half* Bs = smqh + 3*128*40;
    const int mBase = blockIdx.x * 128, nBase = blockIdx.y * 128;
    float C[2][8][4] = {};
    gemm_body_h(g_Ctxh, g_Woh, mBase, nBase, As, Bs, C);

    const int t = threadIdx.x, lane = t & 31, warp = t >> 5;
    const int g = lane >> 2, tg = lane & 3;
    const int wm = warp >> 1, wn = warp & 1;
    #pragma unroll
    for (int mi = 0; mi < 2; mi++) {
        #pragma unroll
        for (int j = 0; j < 8; j++) {
            int n = nBase + wn*64 + j*8 + 2*tg;
            float2 bias = *(const float2*)(bo + n);
            #pragma unroll
            for (int hh = 0; hh < 2; hh++) {
                int m = mBase + wm*32 + mi*16 + g + 8*hh;
                float2 v = make_float2(C[mi][j][hh*2] + bias.x, C[mi][j][hh*2+1] + bias.y);
                *(float2*)(out + (size_t)m*D_ + n) = v;
            }
        }
    }
}

// ---------------------------------------------------------------------------
extern "C" void kernel_launch(void* const* d_in, const int* in_sizes, int n_in,
                              void* d_out, int out_size)
{
    const float* x  = (const float*)d_in[0];
    const float* Wq = (const float*)d_in[1];
    const float* Wk = (const float*)d_in[2];
    const float* Wv = (const float*)d_in[3];
    const float* We = (const float*)d_in[4];
    const float* Wo = (const float*)d_in[5];
    const float* bo = (const float*)d_in[6];
    float* out = (float*)d_out;

    const int gemm_smem = 2 * 3 * 128 * 40 * (int)sizeof(__half);   // 61440
    const int attn_smem = (64*152 + 6*64*72) * (int)sizeof(__half); // 74752
    cudaFuncSetAttribute(qkv_kernel,  cudaFuncAttributeMaxDynamicSharedMemorySize, gemm_smem);
    cudaFuncSetAttribute(attn_kernel, cudaFuncAttributeMaxDynamicSharedMemorySize, attn_smem);
    cudaFuncSetAttribute(out_kernel,  cudaFuncAttributeMaxDynamicSharedMemorySize, gemm_smem);

    const int prep_total = XN_ + 4*WN_ + L_*DH_;
    prep_kernel<<<(prep_total/4 + 255)/256, 256>>>(x, Wq, Wk, Wv, Wo, We);

    qkv_kernel<<<dim3(M_/128, D_/128, 3), 256, gemm_smem>>>();
    attn_kernel<<<dim3(L_/64, BH_), 128, attn_smem>>>();
    out_kernel<<<dim3(M_/128, D_/128), 256, gemm_smem>>>(bo, out);
}